// round 15
// baseline (speedup 1.0000x reference)
#include <cuda_runtime.h>

#define NH_TOTAL (1024 * 8)
#define TILE_ELEMS 4096
#define SMALL_ELEMS ((size_t)NH_TOTAL * 64)
#define BIG_ELEMS   ((size_t)NH_TOTAL * TILE_ELEMS)

static __device__ __forceinline__ float fmap(float x) {
    return x > 0.0f ? x + 1.0f : __expf(x);
}

// 256-bit global load/store (sm_100+), streaming policy
#define LDG256_CS(r, p)                                                       \
    asm("ld.global.cs.v8.f32 {%0,%1,%2,%3,%4,%5,%6,%7}, [%8];"                \
        : "=f"((r)[0]), "=f"((r)[1]), "=f"((r)[2]), "=f"((r)[3]),             \
          "=f"((r)[4]), "=f"((r)[5]), "=f"((r)[6]), "=f"((r)[7])              \
        : "l"(p))

#define STG256_CS(p, r)                                                       \
    asm volatile("st.global.cs.v8.f32 [%0], {%1,%2,%3,%4,%5,%6,%7,%8};"       \
                 :: "l"(p),                                                   \
                    "f"((r)[0]), "f"((r)[1]), "f"((r)[2]), "f"((r)[3]),       \
                    "f"((r)[4]), "f"((r)[5]), "f"((r)[6]), "f"((r)[7])        \
                 : "memory")

__global__ __launch_bounds__(256, 1)
void fr_adamax_kernel(
    const float* __restrict__ q,
    const float* __restrict__ k,
    const float* __restrict__ val,
    const float* __restrict__ Siprev,
    const float* __restrict__ Zi,
    const float* __restrict__ Pi,
    const float* __restrict__ Mi,
    const float* __restrict__ Uiprev,
    const float* __restrict__ Siprev2,
    float* __restrict__ outV,
    float* __restrict__ outSi,
    float* __restrict__ outZ,
    float* __restrict__ outP,
    float* __restrict__ outM,
    float* __restrict__ outU,
    float* __restrict__ outSp)
{
    __shared__ float sQ[2][64], sK[2][64], sVal[2][64];
    __shared__ float sVp[32][65];
    __shared__ float sVred[128];
    __shared__ float sRed[24];
    __shared__ float sMu, sZ;

    const int t = threadIdx.x;
    const int g  = t >> 3;          // d-group for i=0 (0..31); i=1 -> g+32
    const int m0 = (t & 7) << 3;    // m base (8 consecutive)

    const int tile0 = blockIdx.x * 2;
    const size_t sb0 = (size_t)tile0 * 64;
    const size_t bb0 = (size_t)tile0 * TILE_ELEMS;
    const size_t sb1 = sb0 + 64;
    const size_t bb1 = bb0 + TILE_ELEMS;

    // ================= TILE A: front-batch all 5 streams =================
    float svA[2][8], s2vA[2][8], upA[2][8], pvA[2][8], miA[2][8];
#pragma unroll
    for (int i = 0; i < 2; i++) {
        const size_t off = bb0 + (size_t)(t + 256 * i) * 8;
        LDG256_CS(svA[i],  Siprev  + off);
        LDG256_CS(s2vA[i], Siprev2 + off);
        LDG256_CS(upA[i],  Uiprev  + off);
        LDG256_CS(pvA[i],  Pi      + off);
        LDG256_CS(miA[i],  Mi      + off);
    }

    // A small vectors
    float dotvA = 0.0f;
    if (t < 64) {
        float Kf = fmap(k[sb0 + t]);
        float Qf = fmap(q[sb0 + t]);
        float Zn = Zi[sb0 + t] + Kf;
        sQ[0][t] = Qf;
        sK[0][t] = Kf;
        outZ[sb0 + t] = Zn;
        dotvA = Qf * Zn;
    } else if (t < 128) {
        sVal[0][t - 64] = val[sb0 + (t - 64)];
    }
    __syncthreads();

    float vmA[8];
#pragma unroll
    for (int j = 0; j < 8; j++) vmA[j] = sVal[0][m0 + j];

    // -------- Phase 1 A: norms + outU/outSp --------
    float sumU = 0.0f, sumS = 0.0f;
#pragma unroll
    for (int i = 0; i < 2; i++) {
        const size_t off = bb0 + (size_t)(t + 256 * i) * 8;
        const float Kd = sK[0][g + 32 * i];
        float u[8];
#pragma unroll
        for (int j = 0; j < 8; j++) {
            u[j] = Kd * vmA[j];
            float du = u[j] - upA[i][j];
            sumU += du * du;
            float e = svA[i][j] - s2vA[i][j];
            sumS += e * e;
        }
        STG256_CS(outU  + off, u);
        STG256_CS(outSp + off, svA[i]);
    }

    // -------- Issue TILE B: Siprev/Siprev2/Uiprev + small vectors --------
    float svB[2][8], s2vB[2][8], upB[2][8];
#pragma unroll
    for (int i = 0; i < 2; i++) {
        const size_t off = bb1 + (size_t)(t + 256 * i) * 8;
        LDG256_CS(svB[i],  Siprev  + off);
        LDG256_CS(s2vB[i], Siprev2 + off);
        LDG256_CS(upB[i],  Uiprev  + off);
    }
    float dotvB = 0.0f;
    if (t < 64) {
        float Kf = fmap(k[sb1 + t]);
        float Qf = fmap(q[sb1 + t]);
        float Zn = Zi[sb1 + t] + Kf;
        sQ[1][t] = Qf;
        sK[1][t] = Kf;
        outZ[sb1 + t] = Zn;
        dotvB = Qf * Zn;
    } else if (t < 128) {
        sVal[1][t - 64] = val[sb1 + (t - 64)];
    }

    // -------- Reduce A (B loads in flight) --------
#pragma unroll
    for (int o = 16; o > 0; o >>= 1) {
        sumU  += __shfl_down_sync(0xffffffffu, sumU, o);
        sumS  += __shfl_down_sync(0xffffffffu, sumS, o);
        dotvA += __shfl_down_sync(0xffffffffu, dotvA, o);
    }
    if ((t & 31) == 0) {
        const int w = t >> 5;
        sRed[w] = sumU; sRed[8 + w] = sumS; sRed[16 + w] = dotvA;
    }
    __syncthreads();   // also publishes sQ[1]/sK[1]/sVal[1]
    if (t == 0) {
        float aU = 0.0f, aS = 0.0f, aD = 0.0f;
#pragma unroll
        for (int i = 0; i < 8; i++) { aU += sRed[i]; aS += sRed[8+i]; aD += sRed[16+i]; }
        float r  = 1.0f - sqrtf(0.5f * sqrtf(aU) / sqrtf(aS));
        float mu = r * r;
        sMu = fminf(fmaxf(mu, 0.0f), 1.0f - 0.001f);
        sZ  = 1.0f / (aD + 1e-6f);
    }
    __syncthreads();
    const float muA = sMu;
    const float zA  = sZ;

    // -------- Phase 2 A --------
    float v[8];
#pragma unroll
    for (int j = 0; j < 8; j++) v[j] = 0.0f;
#pragma unroll
    for (int i = 0; i < 2; i++) {
        const size_t off = bb0 + (size_t)(t + 256 * i) * 8;
        const int d = g + 32 * i;
        const float Kd = sK[0][d];
        const float Qd = sQ[0][d];
        float pn[8], mn[8], si[8];
#pragma unroll
        for (int j = 0; j < 8; j++) {
            float u = Kd * vmA[j];
            pn[j] = muA * pvA[i][j] - 0.5f * u;
            mn[j] = fmaxf(0.9f * miA[i][j], fabsf(u));
            si[j] = svA[i][j] - pn[j] * rsqrtf(mn[j] + 1e-16f);
            v[j] += Qd * si[j];
        }
        STG256_CS(outP  + off, pn);
        STG256_CS(outM  + off, mn);
        STG256_CS(outSi + off, si);
    }

    // -------- Issue TILE B: Pi/Mi (covers A epilogue + B phase 1) --------
    float pvB[2][8], miB[2][8];
#pragma unroll
    for (int i = 0; i < 2; i++) {
        const size_t off = bb1 + (size_t)(t + 256 * i) * 8;
        LDG256_CS(pvB[i], Pi + off);
        LDG256_CS(miB[i], Mi + off);
    }

    // -------- Epilogue A --------
#pragma unroll
    for (int j = 0; j < 8; j++) sVp[g][m0 + j] = v[j];
    __syncthreads();
    if (t < 128) {
        const int m = t & 63;
        const int h = t >> 6;
        float acc = 0.0f;
#pragma unroll
        for (int gg = 0; gg < 16; gg++) acc += sVp[h * 16 + gg][m];
        sVred[h * 64 + m] = acc;
    }
    __syncthreads();
    if (t < 64) outV[sb0 + t] = (sVred[t] + sVred[64 + t]) * zA;

    // ================= TILE B =================
    float vmB[8];
#pragma unroll
    for (int j = 0; j < 8; j++) vmB[j] = sVal[1][m0 + j];

    // -------- Phase 1 B --------
    sumU = 0.0f; sumS = 0.0f;
#pragma unroll
    for (int i = 0; i < 2; i++) {
        const size_t off = bb1 + (size_t)(t + 256 * i) * 8;
        const float Kd = sK[1][g + 32 * i];
        float u[8];
#pragma unroll
        for (int j = 0; j < 8; j++) {
            u[j] = Kd * vmB[j];
            float du = u[j] - upB[i][j];
            sumU += du * du;
            float e = svB[i][j] - s2vB[i][j];
            sumS += e * e;
        }
        STG256_CS(outU  + off, u);
        STG256_CS(outSp + off, svB[i]);
    }

    // -------- Reduce B --------
#pragma unroll
    for (int o = 16; o > 0; o >>= 1) {
        sumU  += __shfl_down_sync(0xffffffffu, sumU, o);
        sumS  += __shfl_down_sync(0xffffffffu, sumS, o);
        dotvB += __shfl_down_sync(0xffffffffu, dotvB, o);
    }
    __syncthreads();   // epilogue-A readers done with sRed/sVred before overwrite
    if ((t & 31) == 0) {
        const int w = t >> 5;
        sRed[w] = sumU; sRed[8 + w] = sumS; sRed[16 + w] = dotvB;
    }
    __syncthreads();
    if (t == 0) {
        float aU = 0.0f, aS = 0.0f, aD = 0.0f;
#pragma unroll
        for (int i = 0; i < 8; i++) { aU += sRed[i]; aS += sRed[8+i]; aD += sRed[16+i]; }
        float r  = 1.0f - sqrtf(0.5f * sqrtf(aU) / sqrtf(aS));
        float mu = r * r;
        sMu = fminf(fmaxf(mu, 0.0f), 1.0f - 0.001f);
        sZ  = 1.0f / (aD + 1e-6f);
    }
    __syncthreads();
    const float muB = sMu;
    const float zB  = sZ;

    // -------- Phase 2 B --------
#pragma unroll
    for (int j = 0; j < 8; j++) v[j] = 0.0f;
#pragma unroll
    for (int i = 0; i < 2; i++) {
        const size_t off = bb1 + (size_t)(t + 256 * i) * 8;
        const int d = g + 32 * i;
        const float Kd = sK[1][d];
        const float Qd = sQ[1][d];
        float pn[8], mn[8], si[8];
#pragma unroll
        for (int j = 0; j < 8; j++) {
            float u = Kd * vmB[j];
            pn[j] = muB * pvB[i][j] - 0.5f * u;
            mn[j] = fmaxf(0.9f * miB[i][j], fabsf(u));
            si[j] = svB[i][j] - pn[j] * rsqrtf(mn[j] + 1e-16f);
            v[j] += Qd * si[j];
        }
        STG256_CS(outP  + off, pn);
        STG256_CS(outM  + off, mn);
        STG256_CS(outSi + off, si);
    }

    // -------- Epilogue B --------
#pragma unroll
    for (int j = 0; j < 8; j++) sVp[g][m0 + j] = v[j];
    __syncthreads();
    if (t < 128) {
        const int m = t & 63;
        const int h = t >> 6;
        float acc = 0.0f;
#pragma unroll
        for (int gg = 0; gg < 16; gg++) acc += sVp[h * 16 + gg][m];
        sVred[h * 64 + m] = acc;
    }
    __syncthreads();
    if (t < 64) outV[sb1 + t] = (sVred[t] + sVred[64 + t]) * zB;
}

extern "C" void kernel_launch(void* const* d_in, const int* in_sizes, int n_in,
                              void* d_out, int out_size) {
    const float* q    = (const float*)d_in[0];
    const float* k    = (const float*)d_in[1];
    const float* val  = (const float*)d_in[2];
    const float* Sip  = (const float*)d_in[3];
    const float* Zi   = (const float*)d_in[4];
    const float* Pi   = (const float*)d_in[5];
    const float* Mi   = (const float*)d_in[6];
    const float* Uip  = (const float*)d_in[7];
    const float* Sip2 = (const float*)d_in[8];

    float* out = (float*)d_out;
    float* outV  = out;
    float* outSi = outV  + SMALL_ELEMS;
    float* outZ  = outSi + BIG_ELEMS;
    float* outP  = outZ  + SMALL_ELEMS;
    float* outM  = outP  + BIG_ELEMS;
    float* outU  = outM  + BIG_ELEMS;
    float* outSp = outU  + BIG_ELEMS;

    fr_adamax_kernel<<<NH_TOTAL / 2, 256>>>(
        q, k, val, Sip, Zi, Pi, Mi, Uip, Sip2,
        outV, outSi, outZ, outP, outM, outU, outSp);
}

// round 16
// speedup vs baseline: 1.1776x; 1.1776x over previous
#include <cuda_runtime.h>

#define NH_TOTAL (1024 * 8)
#define TILE_ELEMS 4096
#define SMALL_ELEMS ((size_t)NH_TOTAL * 64)
#define BIG_ELEMS   ((size_t)NH_TOTAL * TILE_ELEMS)

static __device__ __forceinline__ float fmap(float x) {
    return x > 0.0f ? x + 1.0f : __expf(x);
}

// 256-bit global load/store (sm_100+), streaming (evict-first) policy
#define LDG256_CS(r, p)                                                       \
    asm("ld.global.cs.v8.f32 {%0,%1,%2,%3,%4,%5,%6,%7}, [%8];"                \
        : "=f"((r)[0]), "=f"((r)[1]), "=f"((r)[2]), "=f"((r)[3]),             \
          "=f"((r)[4]), "=f"((r)[5]), "=f"((r)[6]), "=f"((r)[7])              \
        : "l"(p))

#define STG256_CS(p, r)                                                       \
    asm volatile("st.global.cs.v8.f32 [%0], {%1,%2,%3,%4,%5,%6,%7,%8};"       \
                 :: "l"(p),                                                   \
                    "f"((r)[0]), "f"((r)[1]), "f"((r)[2]), "f"((r)[3]),       \
                    "f"((r)[4]), "f"((r)[5]), "f"((r)[6]), "f"((r)[7])        \
                 : "memory")

__global__ __launch_bounds__(256, 2)
void fr_adamax_kernel(
    const float* __restrict__ q,
    const float* __restrict__ k,
    const float* __restrict__ val,
    const float* __restrict__ Siprev,
    const float* __restrict__ Zi,
    const float* __restrict__ Pi,
    const float* __restrict__ Mi,
    const float* __restrict__ Uiprev,
    const float* __restrict__ Siprev2,
    float* __restrict__ outV,
    float* __restrict__ outSi,
    float* __restrict__ outZ,
    float* __restrict__ outP,
    float* __restrict__ outM,
    float* __restrict__ outU,
    float* __restrict__ outSp)
{
    __shared__ float sQ[64], sK[64], sVal[64];
    __shared__ float sVp[32][65];
    __shared__ float sVred[128];
    __shared__ float sRed[24];
    __shared__ float sMu, sZ;

    const int b = blockIdx.x;
    const int t = threadIdx.x;
    const size_t sb = (size_t)b * 64;
    const size_t bb = (size_t)b * TILE_ELEMS;

    // Thread mapping: chunk c = t + 256*i (i=0,1), elements [8c, 8c+8)
    //   d = c/8 = t/8 + 32*i,  m0 = 8*(t&7)
    const int g  = t >> 3;          // d for i=0 (0..31); d for i=1 is g+32
    const int m0 = (t & 7) << 3;    // m base (8 consecutive)

    // ---- Front-batch ALL 10 LDG.256 per thread (max MLP at issue) ----
    float sv[2][8], s2v[2][8], upv[2][8], pv[2][8], miv[2][8];
#pragma unroll
    for (int i = 0; i < 2; i++) {
        const size_t off = bb + (size_t)(t + 256 * i) * 8;
        LDG256_CS(sv[i],  Siprev  + off);
        LDG256_CS(s2v[i], Siprev2 + off);
        LDG256_CS(upv[i], Uiprev  + off);
        LDG256_CS(pv[i],  Pi      + off);
        LDG256_CS(miv[i], Mi      + off);
    }

    // ---- Small vectors (issued after the big batch; consumed at barrier) ----
    float dotv = 0.0f;
    if (t < 64) {
        float Kf = fmap(k[sb + t]);
        float Qf = fmap(q[sb + t]);
        float Zn = Zi[sb + t] + Kf;
        sQ[t] = Qf;
        sK[t] = Kf;
        outZ[sb + t] = Zn;
        dotv = Qf * Zn;
    } else if (t < 128) {
        sVal[t - 64] = val[sb + (t - 64)];
    }
    __syncthreads();

    float vm[8];
#pragma unroll
    for (int j = 0; j < 8; j++) vm[j] = sVal[m0 + j];

    // ---- Phase 1: norms + mu-independent outputs (outU, outSp) ----
    float sumU = 0.0f, sumS = 0.0f;
#pragma unroll
    for (int i = 0; i < 2; i++) {
        const size_t off = bb + (size_t)(t + 256 * i) * 8;
        const float Kd = sK[g + 32 * i];

        float u[8];
#pragma unroll
        for (int j = 0; j < 8; j++) {
            u[j] = Kd * vm[j];
            float du = u[j] - upv[i][j];
            sumU += du * du;
            float e = sv[i][j] - s2v[i][j];
            sumS += e * e;
        }
        STG256_CS(outU  + off, u);
        STG256_CS(outSp + off, sv[i]);
    }

    // ---- Deterministic 3-way block reduce (sumU, sumS, dot) ----
#pragma unroll
    for (int o = 16; o > 0; o >>= 1) {
        sumU += __shfl_down_sync(0xffffffffu, sumU, o);
        sumS += __shfl_down_sync(0xffffffffu, sumS, o);
        dotv += __shfl_down_sync(0xffffffffu, dotv, o);
    }
    if ((t & 31) == 0) {
        const int w = t >> 5;
        sRed[w]      = sumU;
        sRed[8 + w]  = sumS;
        sRed[16 + w] = dotv;
    }
    __syncthreads();

    if (t == 0) {
        float aU = 0.0f, aS = 0.0f, aD = 0.0f;
#pragma unroll
        for (int i = 0; i < 8; i++) {
            aU += sRed[i]; aS += sRed[8 + i]; aD += sRed[16 + i];
        }
        float r  = 1.0f - sqrtf(0.5f * sqrtf(aU) / sqrtf(aS));   // STEPSIZE=0.5
        float mu = r * r;
        sMu = fminf(fmaxf(mu, 0.0f), 1.0f - 0.001f);              // clip [0,1-DELTA]
        sZ  = 1.0f / (aD + 1e-6f);                                // EPS
    }
    __syncthreads();

    const float mu = sMu;

    // ---- Phase 2: all register-resident; emit Si/Pn/Mn; fold V ----
    float v[8];
#pragma unroll
    for (int j = 0; j < 8; j++) v[j] = 0.0f;

#pragma unroll
    for (int i = 0; i < 2; i++) {
        const size_t off = bb + (size_t)(t + 256 * i) * 8;
        const int d = g + 32 * i;
        const float Kd = sK[d];
        const float Qd = sQ[d];

        float pn[8], mn[8], si[8];
#pragma unroll
        for (int j = 0; j < 8; j++) {
            float u = Kd * vm[j];
            pn[j] = mu * pv[i][j] - 0.5f * u;
            mn[j] = fmaxf(0.9f * miv[i][j], fabsf(u));
            si[j] = sv[i][j] - pn[j] * rsqrtf(mn[j] + 1e-16f);
            v[j] += Qd * si[j];
        }
        STG256_CS(outP  + off, pn);
        STG256_CS(outM  + off, mn);
        STG256_CS(outSi + off, si);
    }

    // ---- Deterministic V reduction over the 32 d-groups ----
#pragma unroll
    for (int j = 0; j < 8; j++) sVp[g][m0 + j] = v[j];
    __syncthreads();

    if (t < 128) {
        const int m = t & 63;
        const int h = t >> 6;           // 0: rows 0-15, 1: rows 16-31
        float acc = 0.0f;
#pragma unroll
        for (int gg = 0; gg < 16; gg++) acc += sVp[h * 16 + gg][m];
        sVred[h * 64 + m] = acc;
    }
    __syncthreads();
    if (t < 64) {
        outV[sb + t] = (sVred[t] + sVred[64 + t]) * sZ;
    }
}

extern "C" void kernel_launch(void* const* d_in, const int* in_sizes, int n_in,
                              void* d_out, int out_size) {
    const float* q    = (const float*)d_in[0];
    const float* k    = (const float*)d_in[1];
    const float* val  = (const float*)d_in[2];
    const float* Sip  = (const float*)d_in[3];
    const float* Zi   = (const float*)d_in[4];
    const float* Pi   = (const float*)d_in[5];
    const float* Mi   = (const float*)d_in[6];
    const float* Uip  = (const float*)d_in[7];
    const float* Sip2 = (const float*)d_in[8];

    float* out = (float*)d_out;
    float* outV  = out;
    float* outSi = outV  + SMALL_ELEMS;
    float* outZ  = outSi + BIG_ELEMS;
    float* outP  = outZ  + SMALL_ELEMS;
    float* outM  = outP  + BIG_ELEMS;
    float* outU  = outM  + BIG_ELEMS;
    float* outSp = outU  + BIG_ELEMS;

    fr_adamax_kernel<<<NH_TOTAL, 256>>>(
        q, k, val, Sip, Zi, Pi, Mi, Uip, Sip2,
        outV, outSi, outZ, outP, outM, outU, outSp);
}